// round 1
// baseline (speedup 1.0000x reference)
#include <cuda_runtime.h>

#define MEMSZ 16384
#define OUTSZ 64
#define NCTX  (MEMSZ + 5 + OUTSZ)   // 16453
#define MAXLOG 64

// opcode values for the 15 experts
__device__ __constant__ float OPV[15] = {1.f, 2.f, 9.f, 10.f, 11.f, 12.f, 13.f, 14.f, 15.f,
                                         3.f, 4.f, 5.f, 6.f, 7.f, 8.f};

__device__ __forceinline__ float sigmoidf_(float x) {
    return 1.0f / (1.0f + expf(-x));
}
__device__ __forceinline__ float siluf_(float x) { return x * sigmoidf_(x); }
__device__ __forceinline__ float silu_thr(float x) {
    // silu_threshold with GATE_SCALE=20: (silu(20x+10) - silu(20x-10)) / 20
    float d = 20.0f * x;
    return (siluf_(d + 10.0f) - siluf_(d - 10.0f)) / 20.0f;
}
__device__ __forceinline__ float eq_gate(float a, float b) {
    float diff = a - b;
    return silu_thr(diff + 0.5f) * silu_thr(0.5f - diff);
}

__global__ void __launch_bounds__(288, 4)
c4_kernel(const float* __restrict__ mem,
          const float* __restrict__ outp,
          const float* __restrict__ ax_in,
          const int* __restrict__ pc_in,
          const int* __restrict__ sp_in,
          const int* __restrict__ bp_in,
          const int* __restrict__ ol_in,
          const int* __restrict__ ns_ptr,
          float* __restrict__ dst) {
    const int b = blockIdx.x;
    const int tid = threadIdx.x;
    const float* mrow = mem + (size_t)b * MEMSZ;
    float* drow = dst + (size_t)b * MEMSZ;

    __shared__ int   s_li[MAXLOG];
    __shared__ float s_lv[MAXLOG];
    __shared__ int   s_n;

    // ---- threads 32..287: stream the 64KB row copy (float4) ----
    if (tid >= 32) {
        const float4* s4 = (const float4*)mrow;
        float4* d4 = (float4*)drow;
        int i = tid - 32;
        #pragma unroll
        for (int k = 0; k < 16; k++)
            d4[i + k * 256] = s4[i + k * 256];
    }

    // ---- thread 0: the 16-step scalar state machine ----
    if (tid == 0) {
        int num_steps = ns_ptr ? ns_ptr[0] : 16;
        if (num_steps > MAXLOG) num_steps = MAXLOG;  // log capacity guard (spec: 16)

        float pc = (float)pc_in[b];
        float sp = (float)sp_in[b];
        float bp = (float)bp_in[b];
        float ax = ax_in[b];
        float ol = (float)ol_in[b];
        const float* orow = outp + (size_t)b * OUTSZ;

        int nlog = 0;

        // read current memory value at idx (with scatter-log overrides)
        auto memval = [&](int idx) -> float {
            float v = __ldg(mrow + idx);
            for (int j = 0; j < nlog; j++)
                if (s_li[j] == idx) v = s_lv[j];
            return v;
        };
        // register/out region value (live state)
        auto regval = [&](int idx) -> float {
            if (idx == MEMSZ)     return pc;
            if (idx == MEMSZ + 1) return sp;
            if (idx == MEMSZ + 2) return bp;
            if (idx == MEMSZ + 3) return ax;
            if (idx == MEMSZ + 4) return ol;
            return __ldg(orow + (idx - MEMSZ - 5));
        };
        auto clampi = [](float a) -> int {
            return (int)fminf(fmaxf(a, 0.0f), (float)(NCTX - 1));
        };

        for (int t = 0; t < num_steps; t++) {
            // --- attend(context, pc): one-hot gather; for ai>=MEM it is an
            //     exact 50/50 tie with mem[ai-MEM] (type-tag score analysis) ---
            int ai_pc = clampi(pc);
            float inst;
            if (ai_pc < MEMSZ) inst = memval(ai_pc);
            else               inst = 0.5f * (regval(ai_pc) + memval(ai_pc - MEMSZ));

            float imm = floorf(inst / 256.0f);
            float opcode = inst - imm * 256.0f;

            // --- attend(context, sp) ---
            int ai_sp = clampi(sp);
            float a, mj, wj;
            int j;
            if (ai_sp < MEMSZ) {
                a = memval(ai_sp);
                j = ai_sp; mj = a; wj = 1.0f;
            } else {
                j = ai_sp - MEMSZ;
                mj = memval(j);
                a = 0.5f * (regval(ai_sp) + mj);
                wj = 0.5f;
            }

            // --- expert outputs ---
            float bb = ax;
            float safeb = (fabsf(bb) < 1e-6f) ? 1e-6f : bb;
            float dv = a / safeb;
            float md = a - safeb * floorf(dv);
            float sh = fminf(fmaxf(bb, 0.0f), 31.0f);
            float eqv = eq_gate(a, bb);
            float lt = sigmoidf_(20.0f * (bb - a - 0.5f));
            float gt = sigmoidf_(20.0f * (a - bb - 0.5f));
            float outs[15] = {
                imm, bp + imm, a + bb, a - bb, a * bb, dv, md,
                a * exp2f(sh), a * exp2f(-sh),
                eqv, 1.0f - eqv, lt, gt, 1.0f - gt, 1.0f - lt
            };

            float gsum = 0.0f, gdot = 0.0f, popg = 0.0f;
            #pragma unroll
            for (int k = 0; k < 15; k++) {
                float g = eq_gate(opcode, OPV[k]);
                gsum += g;
                gdot += g * outs[k];
                if (k >= 2) popg += g;   // POP_MASK: binary ops only
            }
            float new_ax = gdot + (1.0f - gsum) * ax;
            float new_sp = sp + 8.0f * popg;

            // --- soft scatter: lerp mem[j] toward new_ax with weight wj*popg ---
            {
                float nv = mj + (popg * wj) * (new_ax - mj);
                int found = -1;
                for (int q = 0; q < nlog; q++)
                    if (s_li[q] == j) found = q;
                if (found < 0) { s_li[nlog] = j; s_lv[nlog] = nv; nlog++; }
                else           { s_lv[found] = nv; }
            }

            pc += 8.0f;
            sp = new_sp;
            ax = new_ax;
        }
        s_n = nlog;
    }

    __syncthreads();

    // ---- apply patches (log is deduped: one entry per index, parallel-safe) ----
    if (tid < s_n)
        drow[s_li[tid]] = s_lv[tid];
}

extern "C" void kernel_launch(void* const* d_in, const int* in_sizes, int n_in,
                              void* d_out, int out_size) {
    const float* mem  = (const float*)d_in[0];
    const float* outp = (const float*)d_in[1];
    const float* ax   = (const float*)d_in[2];
    const int*   pc   = (const int*)d_in[3];
    const int*   sp   = (const int*)d_in[4];
    const int*   bp   = (const int*)d_in[5];
    const int*   ol   = (const int*)d_in[6];
    const int*   ns   = (n_in > 7) ? (const int*)d_in[7] : nullptr;

    int B = in_sizes[0] / MEMSZ;
    c4_kernel<<<B, 288>>>(mem, outp, ax, pc, sp, bp, ol, ns, (float*)d_out);
}

// round 3
// speedup vs baseline: 2.3009x; 2.3009x over previous
#include <cuda_runtime.h>

#define MEMSZ 16384
#define OUTSZ 64
#define NCTX  (MEMSZ + 5 + OUTSZ)   // 16453
#define FULLW 0xffffffffu

// opcode values for the 15 experts: IMM,LEA,ADD,SUB,MUL,DIV,MOD,SHL,SHR,EQ,NE,LT,GT,LE,GE
__device__ __constant__ float OPV[15] = {1.f, 2.f, 9.f, 10.f, 11.f, 12.f, 13.f, 14.f, 15.f,
                                         3.f, 4.f, 5.f, 6.f, 7.f, 8.f};

__device__ __forceinline__ float sigmoidf_(float x) { return 1.0f / (1.0f + expf(-x)); }
__device__ __forceinline__ float siluf_(float x)    { return x * sigmoidf_(x); }
__device__ __forceinline__ float silu_thr(float x) {
    float d = 20.0f * x;
    return (siluf_(d + 10.0f) - siluf_(d - 10.0f)) / 20.0f;
}
__device__ __forceinline__ float eq_gate(float a, float b) {
    float diff = a - b;
    return silu_thr(diff + 0.5f) * silu_thr(0.5f - diff);
}
__device__ __forceinline__ int clampi_(float a) {
    return (int)fminf(fmaxf(a, 0.0f), (float)(NCTX - 1));
}

__global__ void __launch_bounds__(288)
c4_kernel(const float* __restrict__ mem,
          const float* __restrict__ outp,
          const float* __restrict__ ax_in,
          const int* __restrict__ pc_in,
          const int* __restrict__ sp_in,
          const int* __restrict__ bp_in,
          const int* __restrict__ ol_in,
          const int* __restrict__ ns_ptr,
          float* __restrict__ dst) {
    const int b = blockIdx.x;
    const int tid = threadIdx.x;
    const float* mrow = mem + (size_t)b * MEMSZ;
    float* drow = dst + (size_t)b * MEMSZ;

    // ---- warps 1..8 (threads 32..287): stream the 64KB row copy ----
    if (tid >= 32) {
        const float4* s4 = (const float4*)mrow;
        float4* d4 = (float4*)drow;
        int i = tid - 32;
        #pragma unroll
        for (int k = 0; k < 16; k++)
            d4[i + k * 256] = s4[i + k * 256];
    } else {
        // ---- warp 0: warp-cooperative 16-step state machine ----
        const int lane = tid;
        int num_steps = ns_ptr ? ns_ptr[0] : 16;
        if (num_steps > 32) num_steps = 32;  // log/prefetch capacity (spec: 16)

        float pc = (float)pc_in[b];
        float sp = (float)sp_in[b];
        const float bp = (float)bp_in[b];
        float ax = ax_in[b];
        const float ol = (float)ol_in[b];
        const float* orow = outp + (size_t)b * OUTSZ;

        // scatter log: entry q lives in lane q's registers (deduped, <=32)
        int   log_i = -1;
        float log_v = 0.0f;
        int   nlog = 0;

        // prefetch pc-path instruction words: pc_t = pc0 + 8t (deterministic)
        float praw;
        {
            int api = clampi_(pc + 8.0f * (float)lane);
            int ad = (api < MEMSZ) ? api : (api - MEMSZ);
            praw = __ldg(mrow + ad);
        }

        const int myk = (lane < 15) ? lane : 0;
        const float myopv = OPV[myk];

        for (int t = 0; t < num_steps; t++) {
            // ---- attend(context, pc): one-hot (ai<MEM) or exact 50/50 tie ----
            int api = clampi_(pc);
            int ad = (api < MEMSZ) ? api : (api - MEMSZ);
            float vm = __shfl_sync(FULLW, praw, t);
            {   // apply scatter-log patches
                unsigned m = __ballot_sync(FULLW, (lane < nlog) && (log_i == ad));
                if (m) vm = __shfl_sync(FULLW, log_v, __ffs(m) - 1);
            }
            float inst;
            if (api < MEMSZ) {
                inst = vm;
            } else {
                float rv;
                if      (api == MEMSZ)     rv = pc;
                else if (api == MEMSZ + 1) rv = sp;
                else if (api == MEMSZ + 2) rv = bp;
                else if (api == MEMSZ + 3) rv = ax;
                else if (api == MEMSZ + 4) rv = ol;
                else                       rv = __ldg(orow + (api - MEMSZ - 5));
                inst = 0.5f * (rv + vm);
            }
            float imm = floorf(inst * (1.0f / 256.0f));
            float opcode = inst - imm * 256.0f;

            // ---- attend(context, sp): serial dependent gather ----
            int asp = clampi_(sp);
            int j = (asp < MEMSZ) ? asp : (asp - MEMSZ);
            float mj = __ldg(mrow + j);
            {
                unsigned m = __ballot_sync(FULLW, (lane < nlog) && (log_i == j));
                if (m) mj = __shfl_sync(FULLW, log_v, __ffs(m) - 1);
            }
            float a, wj;
            if (asp < MEMSZ) {
                a = mj; wj = 1.0f;
            } else {
                float rv;
                if      (asp == MEMSZ)     rv = pc;
                else if (asp == MEMSZ + 1) rv = sp;
                else if (asp == MEMSZ + 2) rv = bp;
                else if (asp == MEMSZ + 3) rv = ax;
                else if (asp == MEMSZ + 4) rv = ol;
                else                       rv = __ldg(orow + (asp - MEMSZ - 5));
                a = 0.5f * (rv + mj);
                wj = 0.5f;
            }

            // ---- expert outputs (redundant across lanes; gate is per-lane) ----
            float bb = ax;
            float safeb = (fabsf(bb) < 1e-6f) ? 1e-6f : bb;
            float dv = a / safeb;
            float md = a - safeb * floorf(dv);
            float sh = fminf(fmaxf(bb, 0.0f), 31.0f);
            float eqv = eq_gate(a, bb);
            float lt = sigmoidf_(20.0f * (bb - a - 0.5f));
            float gt = sigmoidf_(20.0f * (a - bb - 0.5f));

            float outk =
                (myk == 0)  ? imm :
                (myk == 1)  ? bp + imm :
                (myk == 2)  ? a + bb :
                (myk == 3)  ? a - bb :
                (myk == 4)  ? a * bb :
                (myk == 5)  ? dv :
                (myk == 6)  ? md :
                (myk == 7)  ? a * exp2f(sh) :
                (myk == 8)  ? a * exp2f(-sh) :
                (myk == 9)  ? eqv :
                (myk == 10) ? 1.0f - eqv :
                (myk == 11) ? lt :
                (myk == 12) ? gt :
                (myk == 13) ? 1.0f - gt :
                              1.0f - lt;

            float g = eq_gate(opcode, myopv);
            float gsum = (lane < 15) ? g : 0.0f;
            float gdot = (lane < 15) ? g * outk : 0.0f;
            float popg = (lane >= 2 && lane < 15) ? g : 0.0f;

            // butterfly reduce (3 values interleaved)
            #pragma unroll
            for (int off = 16; off; off >>= 1) {
                gsum += __shfl_xor_sync(FULLW, gsum, off);
                gdot += __shfl_xor_sync(FULLW, gdot, off);
                popg += __shfl_xor_sync(FULLW, popg, off);
            }

            float new_ax = gdot + (1.0f - gsum) * ax;
            float new_sp = sp + 8.0f * popg;

            // ---- soft scatter: lerp mem[j] toward new_ax, weight wj*popg ----
            {
                float nv = mj + (popg * wj) * (new_ax - mj);
                unsigned m = __ballot_sync(FULLW, (lane < nlog) && (log_i == j));
                int target = m ? (__ffs(m) - 1) : nlog;
                if (lane == target) { log_i = j; log_v = nv; }
                if (!m) nlog++;
            }

            pc += 8.0f;
            sp = new_sp;
            ax = new_ax;
        }

        // defer patch writes until after the copy (below the barrier)
        __syncthreads();
        if (lane < nlog)
            drow[log_i] = log_v;
        return;
    }

    __syncthreads();  // copy warps arrive here (matches warp-0 barrier)
}

extern "C" void kernel_launch(void* const* d_in, const int* in_sizes, int n_in,
                              void* d_out, int out_size) {
    const float* mem  = (const float*)d_in[0];
    const float* outp = (const float*)d_in[1];
    const float* ax   = (const float*)d_in[2];
    const int*   pc   = (const int*)d_in[3];
    const int*   sp   = (const int*)d_in[4];
    const int*   bp   = (const int*)d_in[5];
    const int*   ol   = (const int*)d_in[6];
    const int*   ns   = (n_in > 7) ? (const int*)d_in[7] : nullptr;

    int B = in_sizes[0] / MEMSZ;
    c4_kernel<<<B, 288>>>(mem, outp, ax, pc, sp, bp, ol, ns, (float*)d_out);
}

// round 5
// speedup vs baseline: 5.5395x; 2.4075x over previous
#include <cuda_runtime.h>

#define MEMSZ 16384
#define OUTSZ 64
#define NCTX  (MEMSZ + 5 + OUTSZ)   // 16453
#define MAXST 16                    // num_steps capacity (spec: 16)

// ---------------- kernel 1: streaming row copy ----------------
__global__ void __launch_bounds__(256)
copy_kernel(const float4* __restrict__ src, float4* __restrict__ dst, size_t n4) {
    size_t base = (size_t)blockIdx.x * 4096 + threadIdx.x;  // 4096 float4 per row
    #pragma unroll
    for (int k = 0; k < 16; k++) {
        size_t i = base + (size_t)k * 256;
        if (i < n4) dst[i] = src[i];
    }
}

// ---------------- kernel 2: per-thread state machine + patch writes ----------------
__device__ __forceinline__ float sgm(float x) {        // fast sigmoid, ~ppm rel err
    return __fdividef(1.0f, 1.0f + __expf(-x));
}
__device__ __forceinline__ float silu_(float z) { return z * sgm(z); }
__device__ __forceinline__ float silu_thr(float x) {
    float d = 20.0f * x;
    return (silu_(d + 10.0f) - silu_(d - 10.0f)) * 0.05f;
}
__device__ __forceinline__ float eq_gate(float diff) {
    return silu_thr(diff + 0.5f) * silu_thr(0.5f - diff);
}
__device__ __forceinline__ int clampi_(float a) {
    return (int)fminf(fmaxf(a, 0.0f), (float)(NCTX - 1));
}

__global__ void __launch_bounds__(128)
machine_kernel(const float* __restrict__ mem,
               const float* __restrict__ outp,
               const float* __restrict__ ax_in,
               const int* __restrict__ pc_in,
               const int* __restrict__ sp_in,
               const int* __restrict__ bp_in,
               const int* __restrict__ ol_in,
               const int* __restrict__ ns_ptr,
               float* __restrict__ dst,
               int B) {
    const int r = blockIdx.x * 128 + threadIdx.x;
    if (r >= B) return;

    const float* mrow = mem + (size_t)r * MEMSZ;
    const float* orow = outp + (size_t)r * OUTSZ;
    float* drow = dst + (size_t)r * MEMSZ;

    int ns = ns_ptr ? ns_ptr[0] : MAXST;
    if (ns > MAXST) ns = MAXST;

    float pc = (float)pc_in[r];
    float sp = (float)sp_in[r];
    const float bp = (float)bp_in[r];
    float ax = ax_in[r];
    const float ol = (float)ol_in[r];

    // prefetch pc-path (pc_t = pc0 + 8t, deterministic): 16 loads, full MLP
    float pv[MAXST];
    #pragma unroll
    for (int t = 0; t < MAXST; t++) {
        int api = clampi_(pc + 8.0f * (float)t);
        int ad = (api < MEMSZ) ? api : (api - MEMSZ);
        pv[t] = __ldg(mrow + ad);
    }

    // scatter log in registers (deduped; <= ns entries)
    int   li[MAXST];
    float lv[MAXST];
    int nlog = 0;
    #pragma unroll
    for (int q = 0; q < MAXST; q++) li[q] = -1;

    for (int t = 0; t < ns; t++) {
        // ---- attend(context, pc): one-hot, or exact 50/50 tie for ai>=MEM ----
        int api = clampi_(pc);
        int ad = (api < MEMSZ) ? api : (api - MEMSZ);
        float vm = pv[t];
        #pragma unroll
        for (int q = 0; q < MAXST; q++)
            if (li[q] == ad) vm = lv[q];
        float inst;
        if (api < MEMSZ) {
            inst = vm;
        } else {
            float rv;
            if      (api == MEMSZ)     rv = pc;
            else if (api == MEMSZ + 1) rv = sp;
            else if (api == MEMSZ + 2) rv = bp;
            else if (api == MEMSZ + 3) rv = ax;
            else if (api == MEMSZ + 4) rv = ol;
            else                       rv = __ldg(orow + (api - MEMSZ - 5));
            inst = 0.5f * (rv + vm);
        }
        float imm = floorf(inst * (1.0f / 256.0f));
        float opcode = inst - imm * 256.0f;

        // ---- attend(context, sp) ----
        int asp = clampi_(sp);
        int j = (asp < MEMSZ) ? asp : (asp - MEMSZ);
        float mj = __ldg(mrow + j);
        int fq = -1;
        #pragma unroll
        for (int q = 0; q < MAXST; q++)
            if (li[q] == j) { mj = lv[q]; fq = q; }
        float a, wj;
        if (asp < MEMSZ) {
            a = mj; wj = 1.0f;
        } else {
            float rv;
            if      (asp == MEMSZ)     rv = pc;
            else if (asp == MEMSZ + 1) rv = sp;
            else if (asp == MEMSZ + 2) rv = bp;
            else if (asp == MEMSZ + 3) rv = ax;
            else if (asp == MEMSZ + 4) rv = ol;
            else                       rv = __ldg(orow + (asp - MEMSZ - 5));
            a = 0.5f * (rv + mj);
            wj = 0.5f;
        }

        // ---- expert helper values ----
        float bb = ax;
        float safeb = (fabsf(bb) < 1e-6f) ? 1e-6f : bb;
        float dv = a / safeb;
        float md = a - safeb * floorf(dv);
        float sh = fminf(fmaxf(bb, 0.0f), 31.0f);
        float eqv = eq_gate(a - bb);
        float lt = sgm(20.0f * (bb - a - 0.5f));
        float gt = sgm(20.0f * (a - bb - 0.5f));
        float shl = a * exp2f(sh);
        float shr = a * exp2f(-sh);

        // ---- windowed gates: eq_gate(opcode - v) < 1e-17 for |diff| >= 3 ----
        int vlo = (int)ceilf(opcode - 3.0f);
        float gsum = 0.0f, gdot = 0.0f, popg = 0.0f;
        #pragma unroll
        for (int c = 0; c < 7; c++) {
            int v = vlo + c;
            if (v < 1 || v > 15) continue;
            float g = eq_gate(opcode - (float)v);
            // opcode value -> expert output
            float out;
            switch (v) {
                case 1:  out = imm;        break;   // IMM
                case 2:  out = bp + imm;   break;   // LEA
                case 3:  out = eqv;        break;   // EQ
                case 4:  out = 1.0f - eqv; break;   // NE
                case 5:  out = lt;         break;   // LT
                case 6:  out = gt;         break;   // GT
                case 7:  out = 1.0f - gt;  break;   // LE
                case 8:  out = 1.0f - lt;  break;   // GE
                case 9:  out = a + bb;     break;   // ADD
                case 10: out = a - bb;     break;   // SUB
                case 11: out = a * bb;     break;   // MUL
                case 12: out = dv;         break;   // DIV
                case 13: out = md;         break;   // MOD
                default: out = (v == 14) ? shl : shr; // SHL / SHR
            }
            gsum += g;
            gdot += g * out;
            if (v >= 3) popg += g;                  // POP_MASK: all but IMM/LEA
        }

        float new_ax = gdot + (1.0f - gsum) * ax;
        float new_sp = sp + 8.0f * popg;

        // ---- soft scatter log update at index j ----
        {
            float nv = mj + (popg * wj) * (new_ax - mj);
            int target = (fq >= 0) ? fq : nlog;
            #pragma unroll
            for (int q = 0; q < MAXST; q++)
                if (q == target) { li[q] = j; lv[q] = nv; }
            if (fq < 0) nlog++;
        }

        pc += 8.0f;
        sp = new_sp;
        ax = new_ax;
    }

    // ---- write patches straight into dst (copy kernel already ran) ----
    #pragma unroll
    for (int q = 0; q < MAXST; q++)
        if (q < nlog) drow[li[q]] = lv[q];
}

extern "C" void kernel_launch(void* const* d_in, const int* in_sizes, int n_in,
                              void* d_out, int out_size) {
    const float* mem  = (const float*)d_in[0];
    const float* outp = (const float*)d_in[1];
    const float* ax   = (const float*)d_in[2];
    const int*   pc   = (const int*)d_in[3];
    const int*   sp   = (const int*)d_in[4];
    const int*   bp   = (const int*)d_in[5];
    const int*   ol   = (const int*)d_in[6];
    const int*   ns   = (n_in > 7) ? (const int*)d_in[7] : nullptr;

    int B = in_sizes[0] / MEMSZ;
    size_t n4 = (size_t)B * (MEMSZ / 4);

    copy_kernel<<<B, 256>>>((const float4*)mem, (float4*)d_out, n4);
    machine_kernel<<<(B + 127) / 128, 128>>>(mem, outp, ax, pc, sp, bp, ol, ns,
                                             (float*)d_out, B);
}

// round 9
// speedup vs baseline: 6.7540x; 1.2193x over previous
#include <cuda_runtime.h>

#define MEMSZ 16384
#define OUTSZ 64
#define NCTX  (MEMSZ + 5 + OUTSZ)   // 16453
#define MAXST 16                    // num_steps capacity (spec: 16)

// ---------------- kernel 1: streaming row copy ----------------
__global__ void __launch_bounds__(256)
copy_kernel(const float4* __restrict__ src, float4* __restrict__ dst, size_t n4) {
    size_t base = (size_t)blockIdx.x * 4096 + threadIdx.x;  // 4096 float4 per row
    #pragma unroll
    for (int k = 0; k < 16; k++) {
        size_t i = base + (size_t)k * 256;
        if (i < n4) dst[i] = src[i];
    }
}

// ---------------- kernel 2: per-thread state machine + patch writes ----------------
__device__ __forceinline__ float sgm(float x) {        // fast sigmoid
    return __fdividef(1.0f, 1.0f + __expf(-x));
}

// eq_gate(diff) with a single shared exponential:
//   u = 20*diff; sigmoids needed at u+20, u, 20-u, -u.
//   t = e^-u gives all four: sig(u)=1/(1+t), sig(-u)=1-sig(u),
//   sig(u+20)=1/(1+t*C), sig(20-u)=1/(1+C/t),  C=e^-20.
__device__ __forceinline__ float eq_gate(float diff) {
    const float C = 2.0611536e-9f;          // e^-20
    float u  = 20.0f * diff;
    float t  = __expf(-u);
    float it = __fdividef(1.0f, t);         // e^u
    float s_u  = __fdividef(1.0f, 1.0f + t);        // sig(u)
    float s_nu = 1.0f - s_u;                         // sig(-u)
    float s_up = __fdividef(1.0f, 1.0f + t * C);    // sig(u+20)
    float s_um = __fdividef(1.0f, 1.0f + it * C);   // sig(20-u)
    // silu_thr(diff+0.5) = (silu(u+20) - silu(u)) / 20
    float st1 = ((u + 20.0f) * s_up - u * s_u) * 0.05f;
    // silu_thr(0.5-diff) = (silu(20-u) - silu(-u)) / 20
    float st2 = ((20.0f - u) * s_um + u * s_nu) * 0.05f;
    return st1 * st2;
}
__device__ __forceinline__ int clampi_(float a) {
    return (int)fminf(fmaxf(a, 0.0f), (float)(NCTX - 1));
}

__global__ void __launch_bounds__(32)
machine_kernel(const float* __restrict__ mem,
               const float* __restrict__ outp,
               const float* __restrict__ ax_in,
               const int* __restrict__ pc_in,
               const int* __restrict__ sp_in,
               const int* __restrict__ bp_in,
               const int* __restrict__ ol_in,
               const int* __restrict__ ns_ptr,
               float* __restrict__ dst,
               int B) {
    const int r = blockIdx.x * 32 + threadIdx.x;
    if (r >= B) return;

    const float* mrow = mem + (size_t)r * MEMSZ;
    const float* orow = outp + (size_t)r * OUTSZ;
    float* drow = dst + (size_t)r * MEMSZ;

    int ns = ns_ptr ? ns_ptr[0] : MAXST;
    if (ns > MAXST) ns = MAXST;

    float pc = (float)pc_in[r];
    float sp = (float)sp_in[r];
    const float bp = (float)bp_in[r];
    float ax = ax_in[r];
    const float ol = (float)ol_in[r];

    // prefetch pc-path (pc_t = pc0 + 8t, deterministic): 16 loads, full MLP
    float pv[MAXST];
    #pragma unroll
    for (int t = 0; t < MAXST; t++) {
        int api = clampi_(pc + 8.0f * (float)t);
        int ad = (api < MEMSZ) ? api : (api - MEMSZ);
        pv[t] = __ldg(mrow + ad);
    }

    // scatter log in registers (deduped; <= ns entries)
    int   li[MAXST];
    float lv[MAXST];
    int nlog = 0;
    #pragma unroll
    for (int q = 0; q < MAXST; q++) li[q] = -1;

    for (int t = 0; t < ns; t++) {
        // ---- attend(context, pc): one-hot, or exact 50/50 tie for ai>=MEM ----
        int api = clampi_(pc);
        int ad = (api < MEMSZ) ? api : (api - MEMSZ);
        float vm = pv[t];
        #pragma unroll
        for (int q = 0; q < MAXST; q++)
            if (li[q] == ad) vm = lv[q];
        float inst;
        if (api < MEMSZ) {
            inst = vm;
        } else {
            float rv;
            if      (api == MEMSZ)     rv = pc;
            else if (api == MEMSZ + 1) rv = sp;
            else if (api == MEMSZ + 2) rv = bp;
            else if (api == MEMSZ + 3) rv = ax;
            else if (api == MEMSZ + 4) rv = ol;
            else                       rv = __ldg(orow + (api - MEMSZ - 5));
            inst = 0.5f * (rv + vm);
        }
        float imm = floorf(inst * (1.0f / 256.0f));
        float opcode = inst - imm * 256.0f;

        // ---- attend(context, sp) ----
        int asp = clampi_(sp);
        int j = (asp < MEMSZ) ? asp : (asp - MEMSZ);
        float mj = __ldg(mrow + j);
        int fq = -1;
        #pragma unroll
        for (int q = 0; q < MAXST; q++)
            if (li[q] == j) { mj = lv[q]; fq = q; }
        float a, wj;
        if (asp < MEMSZ) {
            a = mj; wj = 1.0f;
        } else {
            float rv;
            if      (asp == MEMSZ)     rv = pc;
            else if (asp == MEMSZ + 1) rv = sp;
            else if (asp == MEMSZ + 2) rv = bp;
            else if (asp == MEMSZ + 3) rv = ax;
            else if (asp == MEMSZ + 4) rv = ol;
            else                       rv = __ldg(orow + (asp - MEMSZ - 5));
            a = 0.5f * (rv + mj);
            wj = 0.5f;
        }

        // ---- all 15 expert outputs, branchlessly in registers ----
        float bb = ax;
        float safeb = (fabsf(bb) < 1e-6f) ? 1e-6f : bb;
        float dv = a / safeb;
        float md = a - safeb * floorf(dv);
        float sh = fminf(fmaxf(bb, 0.0f), 31.0f);
        float eqv = eq_gate(a - bb);
        float lt = sgm(20.0f * (bb - a - 0.5f));
        float gt = sgm(20.0f * (a - bb - 0.5f));
        float shl = a * exp2f(sh);
        float shr = a * exp2f(-sh);
        float o_add = a + bb, o_sub = a - bb, o_mul = a * bb;
        float o_lea = bp + imm;
        float o_ne = 1.0f - eqv, o_le = 1.0f - gt, o_ge = 1.0f - lt;

        // ---- windowed gates: 5 candidates cover |diff| < 2.5 (rest < 2e-13) ----
        int vlo = (int)ceilf(opcode - 2.5f);
        float gsum = 0.0f, gdot = 0.0f, popg = 0.0f;
        #pragma unroll
        for (int c = 0; c < 5; c++) {
            int v = vlo + c;
            bool ok = (v >= 1) && (v <= 15);
            float g = ok ? eq_gate(opcode - (float)v) : 0.0f;
            // branchless 15-way select (ISETP + FSEL chain, no divergence)
            float out = imm;                       // v==1 IMM
            out = (v == 2)  ? o_lea : out;
            out = (v == 3)  ? eqv   : out;
            out = (v == 4)  ? o_ne  : out;
            out = (v == 5)  ? lt    : out;
            out = (v == 6)  ? gt    : out;
            out = (v == 7)  ? o_le  : out;
            out = (v == 8)  ? o_ge  : out;
            out = (v == 9)  ? o_add : out;
            out = (v == 10) ? o_sub : out;
            out = (v == 11) ? o_mul : out;
            out = (v == 12) ? dv    : out;
            out = (v == 13) ? md    : out;
            out = (v == 14) ? shl   : out;
            out = (v == 15) ? shr   : out;
            gsum += g;
            gdot += g * out;
            popg += (v >= 3) ? g : 0.0f;           // POP_MASK: all but IMM/LEA
        }

        float new_ax = gdot + (1.0f - gsum) * ax;
        float new_sp = sp + 8.0f * popg;

        // ---- soft scatter log update at index j ----
        {
            float nv = mj + (popg * wj) * (new_ax - mj);
            int target = (fq >= 0) ? fq : nlog;
            #pragma unroll
            for (int q = 0; q < MAXST; q++)
                if (q == target) { li[q] = j; lv[q] = nv; }
            if (fq < 0) nlog++;
        }

        pc += 8.0f;
        sp = new_sp;
        ax = new_ax;
    }

    // ---- write patches straight into dst (copy kernel already ran) ----
    #pragma unroll
    for (int q = 0; q < MAXST; q++)
        if (q < nlog) drow[li[q]] = lv[q];
}

extern "C" void kernel_launch(void* const* d_in, const int* in_sizes, int n_in,
                              void* d_out, int out_size) {
    const float* mem  = (const float*)d_in[0];
    const float* outp = (const float*)d_in[1];
    const float* ax   = (const float*)d_in[2];
    const int*   pc   = (const int*)d_in[3];
    const int*   sp   = (const int*)d_in[4];
    const int*   bp   = (const int*)d_in[5];
    const int*   ol   = (const int*)d_in[6];
    const int*   ns   = (n_in > 7) ? (const int*)d_in[7] : nullptr;

    int B = in_sizes[0] / MEMSZ;
    size_t n4 = (size_t)B * (MEMSZ / 4);

    copy_kernel<<<B, 256>>>((const float4*)mem, (float4*)d_out, n4);
    machine_kernel<<<(B + 31) / 32, 32>>>(mem, outp, ax, pc, sp, bp, ol, ns,
                                          (float*)d_out, B);
}